// round 2
// baseline (speedup 1.0000x reference)
#include <cuda_runtime.h>

// ESMGridSample: bilinear grid_sample, zeros padding, align_corners=False
// img:  [16, 1, 1024, 1024] f32
// grid: [16, 1024, 1024, 2] f32 (x,y) in [-1.05, 1.05]
// out:  [16, 1, 1024, 1024] f32
//
// H = W = 1024, H*W = 1<<20. One thread computes 4 consecutive output pixels:
// grid loads become two coalesced float4 (32B/thread), output one float4.

__global__ __launch_bounds__(256)
void ESMGridSample_kernel(const float* __restrict__ img,
                          const float* __restrict__ grid,
                          float* __restrict__ out,
                          int total4)
{
    int t = blockIdx.x * blockDim.x + threadIdx.x;
    if (t >= total4) return;

    int o4 = t << 2;                 // first pixel index of this thread (< 2^24)
    int n  = o4 >> 20;               // batch index (H*W = 2^20)
    const float* __restrict__ im = img + ((long)n << 20);

    const float4 g01 = __ldg(reinterpret_cast<const float4*>(grid + 2 * o4));
    const float4 g23 = __ldg(reinterpret_cast<const float4*>(grid + 2 * o4) + 1);

    float gx[4] = {g01.x, g01.z, g23.x, g23.z};
    float gy[4] = {g01.y, g01.w, g23.y, g23.w};
    float res[4];

#pragma unroll
    for (int i = 0; i < 4; i++) {
        // exact reference expression order: (g + 1) * (dim * 0.5) - 0.5
        float ix = (gx[i] + 1.0f) * 512.0f - 0.5f;
        float iy = (gy[i] + 1.0f) * 512.0f - 0.5f;

        float x0f = floorf(ix);
        float y0f = floorf(iy);
        float wx = ix - x0f;
        float wy = iy - y0f;

        int x0 = (int)x0f;
        int y0 = (int)y0f;
        int x1 = x0 + 1;
        int y1 = y0 + 1;

        // validity masks (unsigned compare folds the >=0 test)
        bool v00m = ((unsigned)x0 < 1024u) & ((unsigned)y0 < 1024u);
        bool v01m = ((unsigned)x1 < 1024u) & ((unsigned)y0 < 1024u);
        bool v10m = ((unsigned)x0 < 1024u) & ((unsigned)y1 < 1024u);
        bool v11m = ((unsigned)x1 < 1024u) & ((unsigned)y1 < 1024u);

        const float* r0 = im + (y0 << 10);   // row y0 (only dereferenced when valid)
        const float* r1 = r0 + 1024;         // row y1

        float v00 = v00m ? __ldg(r0 + x0) : 0.0f;
        float v01 = v01m ? __ldg(r0 + x1) : 0.0f;
        float v10 = v10m ? __ldg(r1 + x0) : 0.0f;
        float v11 = v11m ? __ldg(r1 + x1) : 0.0f;

        // lerp form == reference weighted sum in exact arithmetic; continuity at
        // cell/padding boundaries keeps floor-rounding-flip error at O(1e-5).
        float top = v00 + wx * (v01 - v00);
        float bot = v10 + wx * (v11 - v10);
        res[i] = top + wy * (bot - top);
    }

    float4 r;
    r.x = res[0]; r.y = res[1]; r.z = res[2]; r.w = res[3];
    reinterpret_cast<float4*>(out)[t] = r;
}

extern "C" void kernel_launch(void* const* d_in, const int* in_sizes, int n_in,
                              void* d_out, int out_size)
{
    const float* img  = (const float*)d_in[0];   // source_depth [16,1,1024,1024]
    const float* grid = (const float*)d_in[1];   // pr [16,1024,1024,2]
    // d_in[2] = gt_map (unused by reference)
    float* out = (float*)d_out;

    int total4 = out_size >> 2;                  // 4 pixels per thread
    int threads = 256;
    int blocks = (total4 + threads - 1) / threads;
    ESMGridSample_kernel<<<blocks, threads>>>(img, grid, out, total4);
}

// round 13
// speedup vs baseline: 1.0653x; 1.0653x over previous
#include <cuda_runtime.h>

// ESMGridSample: bilinear grid_sample, zeros padding, align_corners=False
// img:  [16, 1, 1024, 1024] f32
// grid: [16, 1024, 1024, 2] f32 (x,y) in [-1.05, 1.05]
// out:  [16, 1, 1024, 1024] f32
//
// Round-2 change (unmeasured due to repeated infra timeouts; resubmitted):
// per sampled row, fetch one 16B-aligned float4 covering x0..x0+1 when
// (x0&3)<3 (prob 3/4), with a predicated scalar fixup load otherwise.
// Aligned 16B loads are exactly 1 L1 wavefront/lane, cutting gather
// wavefronts ~37% (measured bottleneck at R2 baseline: L1=89%).

__device__ __forceinline__ float sel4(float4 q, int j)
{
    // q[j] for j in {0,1,2,3} via 3 selects (no local-mem dynamic indexing)
    float lo = (j & 1) ? q.y : q.x;
    float hi = (j & 1) ? q.w : q.z;
    return (j & 2) ? hi : lo;
}

__global__ __launch_bounds__(256)
void ESMGridSample_kernel(const float* __restrict__ img,
                          const float* __restrict__ grid,
                          float* __restrict__ out,
                          int total4)
{
    int t = blockIdx.x * blockDim.x + threadIdx.x;
    if (t >= total4) return;

    int o4 = t << 2;                 // first pixel index of this thread (< 2^24)
    int n  = o4 >> 20;               // batch index (H*W = 2^20)
    const float* __restrict__ im = img + ((long)n << 20);

    const float4* gp = reinterpret_cast<const float4*>(grid) + 2 * (long)t;
    const float4 g01 = __ldg(gp);
    const float4 g23 = __ldg(gp + 1);

    float gx[4] = {g01.x, g01.z, g23.x, g23.z};
    float gy[4] = {g01.y, g01.w, g23.y, g23.w};
    float res[4];

#pragma unroll
    for (int i = 0; i < 4; i++) {
        // exact reference expression order: (g + 1) * (dim * 0.5) - 0.5
        float ix = (gx[i] + 1.0f) * 512.0f - 0.5f;
        float iy = (gy[i] + 1.0f) * 512.0f - 0.5f;

        float x0f = floorf(ix);
        float y0f = floorf(iy);
        float wx = ix - x0f;
        float wy = iy - y0f;

        int x0 = (int)x0f;
        int y0 = (int)y0f;
        int x1 = x0 + 1;
        int y1 = y0 + 1;

        bool vx0 = ((unsigned)x0 < 1024u);
        bool vx1 = ((unsigned)x1 < 1024u);
        bool vy0 = ((unsigned)y0 < 1024u);
        bool vy1 = ((unsigned)y1 < 1024u);

        int  a      = x0 & ~3;             // 16B-aligned column base
        int  j0     = x0 & 3;              // position of x0 within the float4
        bool ld4ok  = ((unsigned)a < 1024u);   // a in [0,1020] (a is mult of 4)
        bool within = (j0 < 3);            // x1 also covered by the float4

        const float* r0 = im + (y0 << 10);     // row y0 (deref only when valid)
        const float* r1 = r0 + 1024;           // row y1

        float4 z4 = make_float4(0.f, 0.f, 0.f, 0.f);
        float4 q0 = (vy0 && ld4ok) ? __ldg(reinterpret_cast<const float4*>(r0 + a)) : z4;
        float4 q1 = (vy1 && ld4ok) ? __ldg(reinterpret_cast<const float4*>(r1 + a)) : z4;

        int j1 = j0 + 1;                   // valid select index only when 'within'

        // v00/v10: x0 valid implies a valid; invalid row gives q = 0.
        float v00 = vx0 ? sel4(q0, j0) : 0.0f;
        float v10 = vx0 ? sel4(q1, j0) : 0.0f;

        // v01/v11: from the float4 when covered, else predicated scalar fixup.
        // Fixup also handles x0 = -1 (x1 = 0 valid but a = -4 invalid).
        float v01_in = sel4(q0, j1);
        float v11_in = sel4(q1, j1);
        bool  ex0 = (!within) && vy0 && vx1;
        bool  ex1 = (!within) && vy1 && vx1;
        float v01_ex = ex0 ? __ldg(r0 + x1) : 0.0f;
        float v11_ex = ex1 ? __ldg(r1 + x1) : 0.0f;
        float v01 = within ? (vx1 ? v01_in : 0.0f) : v01_ex;
        float v11 = within ? (vx1 ? v11_in : 0.0f) : v11_ex;

        // lerp form == reference weighted sum in exact arithmetic.
        float top = v00 + wx * (v01 - v00);
        float bot = v10 + wx * (v11 - v10);
        res[i] = top + wy * (bot - top);
    }

    float4 r;
    r.x = res[0]; r.y = res[1]; r.z = res[2]; r.w = res[3];
    reinterpret_cast<float4*>(out)[t] = r;
}

extern "C" void kernel_launch(void* const* d_in, const int* in_sizes, int n_in,
                              void* d_out, int out_size)
{
    const float* img  = (const float*)d_in[0];   // source_depth [16,1,1024,1024]
    const float* grid = (const float*)d_in[1];   // pr [16,1024,1024,2]
    // d_in[2] = gt_map (unused by reference)
    float* out = (float*)d_out;

    int total4 = out_size >> 2;                  // 4 pixels per thread
    int threads = 256;
    int blocks = (total4 + threads - 1) / threads;
    ESMGridSample_kernel<<<blocks, threads>>>(img, grid, out, total4);
}